// round 15
// baseline (speedup 1.0000x reference)
#include <cuda_runtime.h>

// Problem constants
#define BB   8
#define SS   1024
#define CC   768
#define HH   12
#define HDM  64
#define BHN  (BB*HH)     // 96
#define QQ   32

// Scratch (static device allocations — no cudaMalloc allowed)
__device__ float g_q[BHN*SS*HDM];                 // (bh, s, d)
__device__ float g_k[BHN*SS*HDM];
__device__ float g_v[BHN*SS*HDM];
__device__ float g_relh[BHN*QQ*QQ*QQ];            // (bh, i, j, ti)
__device__ float g_relw[BHN*QQ*QQ*QQ];            // (bh, i, j, tj)
__device__ float g_attn[(size_t)BHN*SS*SS];       // (bh, x, y)  ~403 MB
__device__ float g_ctx[BB*SS*CC];                 // (b, s, h*64+d)

// ---------------------------------------------------------------------------
// Kernel 1: qkv = x @ w_qkv^T, scattered into q/k/v with (bh, s, d) layout.
// 128x128 block tile, BK=8, 8x8 per thread, 256 threads.
// ---------------------------------------------------------------------------
__global__ __launch_bounds__(256) void k_qkv(const float* __restrict__ X,
                                             const float* __restrict__ W) {
    __shared__ __align__(16) float As[8][128];
    __shared__ __align__(16) float Bs[8][128];
    const int tid = threadIdx.x;
    const int bm = blockIdx.y * 128;
    const int bn = blockIdx.x * 128;
    const int lr = tid >> 1;            // 0..127
    const int lc = (tid & 1) * 4;       // 0 or 4
    const int tx = tid & 15;            // 0..15  (N)
    const int ty = tid >> 4;            // 0..15  (M)
    float acc[8][8];
#pragma unroll
    for (int i = 0; i < 8; i++)
#pragma unroll
        for (int j = 0; j < 8; j++) acc[i][j] = 0.f;

    for (int k0 = 0; k0 < CC; k0 += 8) {
        float4 a = *(const float4*)(X + (size_t)(bm + lr) * CC + k0 + lc);
        As[lc+0][lr] = a.x; As[lc+1][lr] = a.y; As[lc+2][lr] = a.z; As[lc+3][lr] = a.w;
        float4 b = *(const float4*)(W + (size_t)(bn + lr) * CC + k0 + lc);
        Bs[lc+0][lr] = b.x; Bs[lc+1][lr] = b.y; Bs[lc+2][lr] = b.z; Bs[lc+3][lr] = b.w;
        __syncthreads();
#pragma unroll
        for (int k = 0; k < 8; k++) {
            float af[8], bf[8];
            *(float4*)(af)     = *(const float4*)(&As[k][ty*8]);
            *(float4*)(af + 4) = *(const float4*)(&As[k][ty*8 + 4]);
            *(float4*)(bf)     = *(const float4*)(&Bs[k][tx*8]);
            *(float4*)(bf + 4) = *(const float4*)(&Bs[k][tx*8 + 4]);
#pragma unroll
            for (int i = 0; i < 8; i++)
#pragma unroll
                for (int j = 0; j < 8; j++)
                    acc[i][j] += af[i] * bf[j];
        }
        __syncthreads();
    }

#pragma unroll
    for (int i = 0; i < 8; i++) {
        const int m = bm + ty*8 + i;
        const int b = m >> 10, s = m & 1023;
#pragma unroll
        for (int j = 0; j < 8; j++) {
            const int n = bn + tx*8 + j;
            const int part = n / CC;           // 0=q,1=k,2=v
            const int rem  = n - part * CC;
            const int h = rem >> 6, d = rem & 63;
            float* dst = (part == 0) ? g_q : ((part == 1) ? g_k : g_v);
            dst[((size_t)(b * HH + h) * SS + s) * HDM + d] = acc[i][j];
        }
    }
}

// ---------------------------------------------------------------------------
// Kernel 2: decomposed rel-pos tables.
// rel_h[bh,i,j,ti] = sum_d q[bh,i*32+j,d] * rel_pos_h[i-ti+31, d]
// rel_w[bh,i,j,tj] = sum_d q[bh,i*32+j,d] * rel_pos_w[j-tj+31, d]
// one block per (bh, i)
// ---------------------------------------------------------------------------
__global__ __launch_bounds__(256) void k_rel(const float* __restrict__ rph,
                                             const float* __restrict__ rpw) {
    __shared__ float Qs[32][64];
    __shared__ float Rh[32][64];
    __shared__ float Rw[63][64];
    const int bh = blockIdx.x;
    const int qi = blockIdx.y;
    const int tid = threadIdx.x;
    const float* qp = g_q + ((size_t)bh * SS + (size_t)qi * QQ) * HDM;

    for (int idx = tid; idx < 32 * 64; idx += 256) {
        const int r = idx >> 6, d = idx & 63;
        Qs[r][d] = qp[(size_t)r * HDM + d];
        Rh[r][d] = rph[(size_t)(qi - r + 31) * HDM + d];
    }
    for (int idx = tid; idx < 63 * 64; idx += 256) {
        Rw[idx >> 6][idx & 63] = rpw[idx];
    }
    __syncthreads();

    float* relh = g_relh + ((size_t)bh * QQ + qi) * QQ * QQ;
    float* relw = g_relw + ((size_t)bh * QQ + qi) * QQ * QQ;
    for (int p = tid; p < 32 * 32; p += 256) {
        const int j = p >> 5, t = p & 31;
        const float* qrow = Qs[j];
        const float* rhr  = Rh[t];
        const float* rwr  = Rw[j - t + 31];
        float sh = 0.f, sw = 0.f;
#pragma unroll
        for (int d = 0; d < 64; d++) {
            sh += qrow[d] * rhr[d];
            sw += qrow[d] * rwr[d];
        }
        relh[(size_t)j * QQ + t] = sh;
        relw[(size_t)j * QQ + t] = sw;
    }
}

// ---------------------------------------------------------------------------
// Kernel 3: attn[bh,x,y] = 0.125 * q[bh,x,:]·k[bh,y,:] + relh + relw
// batched 1024x1024x64 GEMM, 128x128 tiles, grid (8,8,96)
// ---------------------------------------------------------------------------
__global__ __launch_bounds__(256) void k_scores() {
    __shared__ __align__(16) float As[8][128];
    __shared__ __align__(16) float Bs[8][128];
    const int tid = threadIdx.x;
    const int bh = blockIdx.z;
    const int bm = blockIdx.y * 128;
    const int bn = blockIdx.x * 128;
    const float* Qp = g_q + (size_t)bh * SS * HDM;
    const float* Kp = g_k + (size_t)bh * SS * HDM;
    const int lr = tid >> 1;
    const int lc = (tid & 1) * 4;
    const int tx = tid & 15, ty = tid >> 4;
    float acc[8][8];
#pragma unroll
    for (int i = 0; i < 8; i++)
#pragma unroll
        for (int j = 0; j < 8; j++) acc[i][j] = 0.f;

    for (int k0 = 0; k0 < HDM; k0 += 8) {
        float4 a = *(const float4*)(Qp + (size_t)(bm + lr) * HDM + k0 + lc);
        As[lc+0][lr] = a.x; As[lc+1][lr] = a.y; As[lc+2][lr] = a.z; As[lc+3][lr] = a.w;
        float4 b = *(const float4*)(Kp + (size_t)(bn + lr) * HDM + k0 + lc);
        Bs[lc+0][lr] = b.x; Bs[lc+1][lr] = b.y; Bs[lc+2][lr] = b.z; Bs[lc+3][lr] = b.w;
        __syncthreads();
#pragma unroll
        for (int k = 0; k < 8; k++) {
            float af[8], bf[8];
            *(float4*)(af)     = *(const float4*)(&As[k][ty*8]);
            *(float4*)(af + 4) = *(const float4*)(&As[k][ty*8 + 4]);
            *(float4*)(bf)     = *(const float4*)(&Bs[k][tx*8]);
            *(float4*)(bf + 4) = *(const float4*)(&Bs[k][tx*8 + 4]);
#pragma unroll
            for (int i = 0; i < 8; i++)
#pragma unroll
                for (int j = 0; j < 8; j++)
                    acc[i][j] += af[i] * bf[j];
        }
        __syncthreads();
    }

    const float* rh = g_relh + (size_t)bh * QQ * QQ * QQ;
    const float* rw = g_relw + (size_t)bh * QQ * QQ * QQ;
    float* out = g_attn + (size_t)bh * SS * SS;
#pragma unroll
    for (int i = 0; i < 8; i++) {
        const int x = bm + ty*8 + i;
        const int qi = x >> 5, qj = x & 31;
        const float* rhrow = rh + ((size_t)qi * QQ + qj) * QQ;
        const float* rwrow = rw + ((size_t)qi * QQ + qj) * QQ;
#pragma unroll
        for (int j = 0; j < 8; j++) {
            const int y = bn + tx*8 + j;
            const int ti = y >> 5, tj = y & 31;
            out[(size_t)x * SS + y] = acc[i][j] * 0.125f + rhrow[ti] + rwrow[tj];
        }
    }
}

// ---------------------------------------------------------------------------
// Kernel 4: row softmax over 1024, one block per row, float4 per thread.
// ---------------------------------------------------------------------------
__global__ __launch_bounds__(256) void k_softmax() {
    __shared__ float rm[8];
    __shared__ float rs[8];
    const size_t row = blockIdx.x;
    float* p = g_attn + row * SS;
    const int tid = threadIdx.x;
    float4 v = reinterpret_cast<const float4*>(p)[tid];

    float m = fmaxf(fmaxf(v.x, v.y), fmaxf(v.z, v.w));
#pragma unroll
    for (int o = 16; o; o >>= 1) m = fmaxf(m, __shfl_xor_sync(0xffffffffu, m, o));
    if ((tid & 31) == 0) rm[tid >> 5] = m;
    __syncthreads();
    float gm = rm[0];
#pragma unroll
    for (int w = 1; w < 8; w++) gm = fmaxf(gm, rm[w]);

    v.x = __expf(v.x - gm);
    v.y = __expf(v.y - gm);
    v.z = __expf(v.z - gm);
    v.w = __expf(v.w - gm);
    float s = v.x + v.y + v.z + v.w;
#pragma unroll
    for (int o = 16; o; o >>= 1) s += __shfl_xor_sync(0xffffffffu, s, o);
    if ((tid & 31) == 0) rs[tid >> 5] = s;
    __syncthreads();
    float gs = rs[0];
#pragma unroll
    for (int w = 1; w < 8; w++) gs += rs[w];

    const float inv = 1.0f / gs;
    v.x *= inv; v.y *= inv; v.z *= inv; v.w *= inv;
    reinterpret_cast<float4*>(p)[tid] = v;
}

// ---------------------------------------------------------------------------
// Kernel 5: ctx[b,s,h*64+d] = sum_y attn[bh,s,y] * v[bh,y,d]
// per bh: 1024x64x1024 GEMM. BM=128, BN=64, BK=16, 8x4 per thread.
// ---------------------------------------------------------------------------
__global__ __launch_bounds__(256) void k_av() {
    __shared__ __align__(16) float As[16][128];
    __shared__ __align__(16) float Bs[16][64];
    const int tid = threadIdx.x;
    const int bh = blockIdx.y;
    const int bm = blockIdx.x * 128;
    const float* Ap = g_attn + (size_t)bh * SS * SS;
    const float* Vp = g_v + (size_t)bh * SS * HDM;
    const int lrA = tid >> 1;             // 0..127
    const int lcA = (tid & 1) * 8;        // 0 or 8
    const int lrB = tid >> 4;             // 0..15
    const int lcB = (tid & 15) * 4;       // 0..60
    const int tx = tid & 15;              // N: tx*4
    const int ty = tid >> 4;              // M: ty*8
    float acc[8][4];
#pragma unroll
    for (int i = 0; i < 8; i++)
#pragma unroll
        for (int j = 0; j < 4; j++) acc[i][j] = 0.f;

    for (int k0 = 0; k0 < SS; k0 += 16) {
        const float* arow = Ap + (size_t)(bm + lrA) * SS + k0 + lcA;
        float4 a0 = *(const float4*)(arow);
        float4 a1 = *(const float4*)(arow + 4);
        As[lcA+0][lrA] = a0.x; As[lcA+1][lrA] = a0.y; As[lcA+2][lrA] = a0.z; As[lcA+3][lrA] = a0.w;
        As[lcA+4][lrA] = a1.x; As[lcA+5][lrA] = a1.y; As[lcA+6][lrA] = a1.z; As[lcA+7][lrA] = a1.w;
        *(float4*)(&Bs[lrB][lcB]) = *(const float4*)(Vp + (size_t)(k0 + lrB) * HDM + lcB);
        __syncthreads();
#pragma unroll
        for (int k = 0; k < 16; k++) {
            float af[8], bf[4];
            *(float4*)(af)     = *(const float4*)(&As[k][ty*8]);
            *(float4*)(af + 4) = *(const float4*)(&As[k][ty*8 + 4]);
            *(float4*)(bf)     = *(const float4*)(&Bs[k][tx*4]);
#pragma unroll
            for (int i = 0; i < 8; i++)
#pragma unroll
                for (int j = 0; j < 4; j++)
                    acc[i][j] += af[i] * bf[j];
        }
        __syncthreads();
    }

    const int b = bh / HH, h = bh % HH;
#pragma unroll
    for (int i = 0; i < 8; i++) {
        const int s = bm + ty*8 + i;
        float* dst = g_ctx + (size_t)(b * SS + s) * CC + h * HDM + tx * 4;
        *(float4*)dst = make_float4(acc[i][0], acc[i][1], acc[i][2], acc[i][3]);
    }
}

// ---------------------------------------------------------------------------
// Kernel 6: out = ctx @ w_out^T + b_out. M=8192, N=768, K=768.
// ---------------------------------------------------------------------------
__global__ __launch_bounds__(256) void k_proj(const float* __restrict__ W,
                                              const float* __restrict__ bias,
                                              float* __restrict__ out) {
    __shared__ __align__(16) float As[8][128];
    __shared__ __align__(16) float Bs[8][128];
    const int tid = threadIdx.x;
    const int bm = blockIdx.y * 128;
    const int bn = blockIdx.x * 128;
    const int lr = tid >> 1;
    const int lc = (tid & 1) * 4;
    const int tx = tid & 15, ty = tid >> 4;
    float acc[8][8];
#pragma unroll
    for (int i = 0; i < 8; i++)
#pragma unroll
        for (int j = 0; j < 8; j++) acc[i][j] = 0.f;

    for (int k0 = 0; k0 < CC; k0 += 8) {
        float4 a = *(const float4*)(g_ctx + (size_t)(bm + lr) * CC + k0 + lc);
        As[lc+0][lr] = a.x; As[lc+1][lr] = a.y; As[lc+2][lr] = a.z; As[lc+3][lr] = a.w;
        float4 b = *(const float4*)(W + (size_t)(bn + lr) * CC + k0 + lc);
        Bs[lc+0][lr] = b.x; Bs[lc+1][lr] = b.y; Bs[lc+2][lr] = b.z; Bs[lc+3][lr] = b.w;
        __syncthreads();
#pragma unroll
        for (int k = 0; k < 8; k++) {
            float af[8], bf[8];
            *(float4*)(af)     = *(const float4*)(&As[k][ty*8]);
            *(float4*)(af + 4) = *(const float4*)(&As[k][ty*8 + 4]);
            *(float4*)(bf)     = *(const float4*)(&Bs[k][tx*8]);
            *(float4*)(bf + 4) = *(const float4*)(&Bs[k][tx*8 + 4]);
#pragma unroll
            for (int i = 0; i < 8; i++)
#pragma unroll
                for (int j = 0; j < 8; j++)
                    acc[i][j] += af[i] * bf[j];
        }
        __syncthreads();
    }

#pragma unroll
    for (int i = 0; i < 8; i++) {
        const int m = bm + ty*8 + i;
#pragma unroll
        for (int j = 0; j < 8; j++) {
            const int n = bn + tx*8 + j;
            out[(size_t)m * CC + n] = acc[i][j] + bias[n];
        }
    }
}

// ---------------------------------------------------------------------------
extern "C" void kernel_launch(void* const* d_in, const int* in_sizes, int n_in,
                              void* d_out, int out_size) {
    const float* x     = (const float*)d_in[0];
    const float* w_qkv = (const float*)d_in[1];
    const float* w_out = (const float*)d_in[2];
    const float* b_out = (const float*)d_in[3];
    const float* rph   = (const float*)d_in[4];
    const float* rpw   = (const float*)d_in[5];
    float* out = (float*)d_out;

    k_qkv   <<<dim3(2304/128, 8192/128), 256>>>(x, w_qkv);
    k_rel   <<<dim3(BHN, QQ), 256>>>(rph, rpw);
    k_scores<<<dim3(8, 8, BHN), 256>>>();
    k_softmax<<<dim3(BHN * SS), 256>>>();
    k_av    <<<dim3(8, BHN), 256>>>();
    k_proj  <<<dim3(768/128, 8192/128), 256>>>(w_out, b_out, out);
}

// round 16
// speedup vs baseline: 2.2672x; 2.2672x over previous
#include <cuda_runtime.h>
#include <cstdint>

// Problem constants
#define BB   8
#define SS   1024
#define CC   768
#define HH   12
#define HDM  64
#define BHN  (BB*HH)     // 96
#define QQ   32

// Scratch (static device allocations — no cudaMalloc allowed)
__device__ float g_q[BHN*SS*HDM];                 // (bh, s, d)
__device__ float g_k[BHN*SS*HDM];
__device__ float g_v[BHN*SS*HDM];
__device__ float g_relh[BHN*QQ*QQ*QQ];            // (bh, i, j, ti)
__device__ float g_relw[BHN*QQ*QQ*QQ];            // (bh, i, j, tj)
__device__ float g_attn[(size_t)BHN*SS*SS];       // (bh, x, y)  ~403 MB
__device__ float g_ctx[BB*SS*CC];                 // (b, s, h*64+d)

// ---------------------------------------------------------------------------
// tf32 helpers
// ---------------------------------------------------------------------------
__device__ __forceinline__ unsigned f2tf(float x) {
    unsigned u;
    asm("cvt.rna.tf32.f32 %0, %1;" : "=r"(u) : "f"(x));
    return u;
}

// D += A*B  (m16n8k8, tf32 in, fp32 accum), in-place accumulators
__device__ __forceinline__ void mma8(float* c, const unsigned* a, const unsigned* b) {
    asm volatile(
        "mma.sync.aligned.m16n8k8.row.col.f32.tf32.tf32.f32 "
        "{%0,%1,%2,%3}, {%4,%5,%6,%7}, {%8,%9}, {%0,%1,%2,%3};"
        : "+f"(c[0]), "+f"(c[1]), "+f"(c[2]), "+f"(c[3])
        : "r"(a[0]), "r"(a[1]), "r"(a[2]), "r"(a[3]), "r"(b[0]), "r"(b[1]));
}

// ---------------------------------------------------------------------------
// Shared 128x128 GEMM mainloop: C[128,128] = A[128,K] * B[128,K]^T
// A,B row-major with leading dims lda/ldb (both K-contiguous).
// acc layout: acc[im][t][4] per warp; warp = 32x64 tile (2 m-tiles x 8 n-tiles)
// Smem: [row][k] with pad 4 -> conflict-free fragment reads.
// ---------------------------------------------------------------------------
__device__ __forceinline__ void gemm_tile_128x128(
    const float* __restrict__ A, int lda,
    const float* __restrict__ B, int ldb,
    int K, unsigned (*As)[36], unsigned (*Bs)[36],
    float acc[2][8][4])
{
    const int tid  = threadIdx.x;
    const int lane = tid & 31;
    const int warp = tid >> 5;
    const int wm = warp >> 1;   // 0..3
    const int wn = warp & 1;    // 0..1
    const int grp = lane >> 2;  // 0..7
    const int tig = lane & 3;   // 0..3

    for (int k0 = 0; k0 < K; k0 += 32) {
#pragma unroll
        for (int i = 0; i < 4; i++) {
            const int idx = tid + i * 256;
            const int r = idx >> 3;
            const int c = (idx & 7) * 4;
            float4 a = *(const float4*)(A + (size_t)r * lda + k0 + c);
            *(uint4*)&As[r][c] = make_uint4(f2tf(a.x), f2tf(a.y), f2tf(a.z), f2tf(a.w));
            float4 b = *(const float4*)(B + (size_t)r * ldb + k0 + c);
            *(uint4*)&Bs[r][c] = make_uint4(f2tf(b.x), f2tf(b.y), f2tf(b.z), f2tf(b.w));
        }
        __syncthreads();
#pragma unroll
        for (int kk = 0; kk < 32; kk += 8) {
            unsigned bf[8][2];
#pragma unroll
            for (int t = 0; t < 8; t++) {
                const int n0 = wn * 64 + t * 8 + grp;
                bf[t][0] = Bs[n0][kk + tig];
                bf[t][1] = Bs[n0][kk + tig + 4];
            }
#pragma unroll
            for (int im = 0; im < 2; im++) {
                const int m0 = wm * 32 + im * 16 + grp;
                unsigned af[4];
                af[0] = As[m0    ][kk + tig];
                af[1] = As[m0 + 8][kk + tig];
                af[2] = As[m0    ][kk + tig + 4];
                af[3] = As[m0 + 8][kk + tig + 4];
#pragma unroll
                for (int t = 0; t < 8; t++) mma8(acc[im][t], af, bf[t]);
            }
        }
        __syncthreads();
    }
}

// ---------------------------------------------------------------------------
// Kernel 1: qkv = x @ w_qkv^T, scattered into q/k/v (bh, s, d).
// ---------------------------------------------------------------------------
__global__ __launch_bounds__(256) void k_qkv(const float* __restrict__ X,
                                             const float* __restrict__ W) {
    __shared__ __align__(16) unsigned As[128][36];
    __shared__ __align__(16) unsigned Bs[128][36];
    const int bm = blockIdx.y * 128;
    const int bn = blockIdx.x * 128;

    float acc[2][8][4];
#pragma unroll
    for (int i = 0; i < 2; i++)
#pragma unroll
        for (int t = 0; t < 8; t++)
#pragma unroll
            for (int v = 0; v < 4; v++) acc[i][t][v] = 0.f;

    gemm_tile_128x128(X + (size_t)bm * CC, CC, W + (size_t)bn * CC, CC, CC, As, Bs, acc);

    const int tid = threadIdx.x;
    const int lane = tid & 31, warp = tid >> 5;
    const int wm = warp >> 1, wn = warp & 1;
    const int grp = lane >> 2, tig = lane & 3;

#pragma unroll
    for (int im = 0; im < 2; im++) {
        const int r0 = bm + wm * 32 + im * 16 + grp;
        const int r1 = r0 + 8;
        const int b0i = r0 >> 10, s0 = r0 & 1023;
        const int b1i = r1 >> 10, s1 = r1 & 1023;
#pragma unroll
        for (int t = 0; t < 8; t++) {
            const int col  = bn + wn * 64 + t * 8 + tig * 2;
            const int part = col / CC;            // 0=q,1=k,2=v
            const int rem  = col - part * CC;
            const int h = rem >> 6, d = rem & 63; // d even -> pair stays in head
            float* dst = (part == 0) ? g_q : ((part == 1) ? g_k : g_v);
            float* p0 = dst + ((size_t)(b0i * HH + h) * SS + s0) * HDM + d;
            float* p1 = dst + ((size_t)(b1i * HH + h) * SS + s1) * HDM + d;
            *(float2*)p0 = make_float2(acc[im][t][0], acc[im][t][1]);
            *(float2*)p1 = make_float2(acc[im][t][2], acc[im][t][3]);
        }
    }
}

// ---------------------------------------------------------------------------
// Kernel 2: decomposed rel-pos tables (fp32, unchanged).
// ---------------------------------------------------------------------------
__global__ __launch_bounds__(256) void k_rel(const float* __restrict__ rph,
                                             const float* __restrict__ rpw) {
    __shared__ float Qs[32][64];
    __shared__ float Rh[32][64];
    __shared__ float Rw[63][64];
    const int bh = blockIdx.x;
    const int qi = blockIdx.y;
    const int tid = threadIdx.x;
    const float* qp = g_q + ((size_t)bh * SS + (size_t)qi * QQ) * HDM;

    for (int idx = tid; idx < 32 * 64; idx += 256) {
        const int r = idx >> 6, d = idx & 63;
        Qs[r][d] = qp[(size_t)r * HDM + d];
        Rh[r][d] = rph[(size_t)(qi - r + 31) * HDM + d];
    }
    for (int idx = tid; idx < 63 * 64; idx += 256) {
        Rw[idx >> 6][idx & 63] = rpw[idx];
    }
    __syncthreads();

    float* relh = g_relh + ((size_t)bh * QQ + qi) * QQ * QQ;
    float* relw = g_relw + ((size_t)bh * QQ + qi) * QQ * QQ;
    for (int p = tid; p < 32 * 32; p += 256) {
        const int j = p >> 5, t = p & 31;
        const float* qrow = Qs[j];
        const float* rhr  = Rh[t];
        const float* rwr  = Rw[j - t + 31];
        float sh = 0.f, sw = 0.f;
#pragma unroll
        for (int d = 0; d < 64; d++) {
            sh += qrow[d] * rhr[d];
            sw += qrow[d] * rwr[d];
        }
        relh[(size_t)j * QQ + t] = sh;
        relw[(size_t)j * QQ + t] = sw;
    }
}

// ---------------------------------------------------------------------------
// Kernel 3: attn[bh,x,y] = 0.125 * q·k + relh + relw   (tf32 mma)
// ---------------------------------------------------------------------------
__global__ __launch_bounds__(256) void k_scores() {
    __shared__ __align__(16) unsigned As[128][36];
    __shared__ __align__(16) unsigned Bs[128][36];
    const int bh = blockIdx.z;
    const int bm = blockIdx.y * 128;
    const int bn = blockIdx.x * 128;

    float acc[2][8][4];
#pragma unroll
    for (int i = 0; i < 2; i++)
#pragma unroll
        for (int t = 0; t < 8; t++)
#pragma unroll
            for (int v = 0; v < 4; v++) acc[i][t][v] = 0.f;

    gemm_tile_128x128(g_q + (size_t)bh * SS * HDM + (size_t)bm * HDM, HDM,
                      g_k + (size_t)bh * SS * HDM + (size_t)bn * HDM, HDM,
                      HDM, As, Bs, acc);

    const int tid = threadIdx.x;
    const int lane = tid & 31, warp = tid >> 5;
    const int wm = warp >> 1, wn = warp & 1;
    const int grp = lane >> 2, tig = lane & 3;

    const float* rh = g_relh + (size_t)bh * QQ * QQ * QQ;
    const float* rw = g_relw + (size_t)bh * QQ * QQ * QQ;
    float* out = g_attn + (size_t)bh * SS * SS;

#pragma unroll
    for (int im = 0; im < 2; im++) {
        const int x0 = bm + wm * 32 + im * 16 + grp;
        const int x1 = x0 + 8;
#pragma unroll
        for (int t = 0; t < 8; t++) {
            const int y  = bn + wn * 64 + t * 8 + tig * 2;   // even
            const int ti = y >> 5;
            const int tj0 = y & 31, tj1 = (y + 1) & 31;
            {
                const int qi = x0 >> 5, qj = x0 & 31;
                const float* rhrow = rh + ((size_t)qi * QQ + qj) * QQ;
                const float* rwrow = rw + ((size_t)qi * QQ + qj) * QQ;
                const float bias = rhrow[ti];
                *(float2*)(out + (size_t)x0 * SS + y) = make_float2(
                    acc[im][t][0] * 0.125f + bias + rwrow[tj0],
                    acc[im][t][1] * 0.125f + bias + rwrow[tj1]);
            }
            {
                const int qi = x1 >> 5, qj = x1 & 31;
                const float* rhrow = rh + ((size_t)qi * QQ + qj) * QQ;
                const float* rwrow = rw + ((size_t)qi * QQ + qj) * QQ;
                const float bias = rhrow[ti];
                *(float2*)(out + (size_t)x1 * SS + y) = make_float2(
                    acc[im][t][2] * 0.125f + bias + rwrow[tj0],
                    acc[im][t][3] * 0.125f + bias + rwrow[tj1]);
            }
        }
    }
}

// ---------------------------------------------------------------------------
// Kernel 4: row softmax over 1024 (unchanged — 70% DRAM already).
// ---------------------------------------------------------------------------
__global__ __launch_bounds__(256) void k_softmax() {
    __shared__ float rm[8];
    __shared__ float rs[8];
    const size_t row = blockIdx.x;
    float* p = g_attn + row * SS;
    const int tid = threadIdx.x;
    float4 v = reinterpret_cast<const float4*>(p)[tid];

    float m = fmaxf(fmaxf(v.x, v.y), fmaxf(v.z, v.w));
#pragma unroll
    for (int o = 16; o; o >>= 1) m = fmaxf(m, __shfl_xor_sync(0xffffffffu, m, o));
    if ((tid & 31) == 0) rm[tid >> 5] = m;
    __syncthreads();
    float gm = rm[0];
#pragma unroll
    for (int w = 1; w < 8; w++) gm = fmaxf(gm, rm[w]);

    v.x = __expf(v.x - gm);
    v.y = __expf(v.y - gm);
    v.z = __expf(v.z - gm);
    v.w = __expf(v.w - gm);
    float s = v.x + v.y + v.z + v.w;
#pragma unroll
    for (int o = 16; o; o >>= 1) s += __shfl_xor_sync(0xffffffffu, s, o);
    if ((tid & 31) == 0) rs[tid >> 5] = s;
    __syncthreads();
    float gs = rs[0];
#pragma unroll
    for (int w = 1; w < 8; w++) gs += rs[w];

    const float inv = 1.0f / gs;
    v.x *= inv; v.y *= inv; v.z *= inv; v.w *= inv;
    reinterpret_cast<float4*>(p)[tid] = v;
}

// ---------------------------------------------------------------------------
// Kernel 5: ctx = attn @ V   (tf32 mma).  Per bh: M=1024, N=64, K=1024.
// BM=128, BN=64. Warp tile 32x32 (2 m-tiles x 4 n-tiles).
// V stored in smem as [k][n] pad 8 -> conflict-free B-fragment reads.
// ---------------------------------------------------------------------------
__global__ __launch_bounds__(256) void k_av() {
    __shared__ __align__(16) unsigned As[128][36];
    __shared__ __align__(16) unsigned Bsv[32][72];
    const int bh = blockIdx.y;
    const int bm = blockIdx.x * 128;
    const float* A = g_attn + (size_t)bh * SS * SS + (size_t)bm * SS;
    const float* V = g_v + (size_t)bh * SS * HDM;

    const int tid = threadIdx.x;
    const int lane = tid & 31, warp = tid >> 5;
    const int wm = warp >> 1, wn = warp & 1;
    const int grp = lane >> 2, tig = lane & 3;

    float acc[2][4][4];
#pragma unroll
    for (int i = 0; i < 2; i++)
#pragma unroll
        for (int t = 0; t < 4; t++)
#pragma unroll
            for (int v = 0; v < 4; v++) acc[i][t][v] = 0.f;

    for (int k0 = 0; k0 < SS; k0 += 32) {
#pragma unroll
        for (int i = 0; i < 4; i++) {
            const int idx = tid + i * 256;
            const int r = idx >> 3;
            const int c = (idx & 7) * 4;
            float4 a = *(const float4*)(A + (size_t)r * SS + k0 + c);
            *(uint4*)&As[r][c] = make_uint4(f2tf(a.x), f2tf(a.y), f2tf(a.z), f2tf(a.w));
        }
#pragma unroll
        for (int i = 0; i < 2; i++) {
            const int idx = tid + i * 256;
            const int r = idx >> 4;
            const int c = (idx & 15) * 4;
            float4 b = *(const float4*)(V + (size_t)(k0 + r) * HDM + c);
            *(uint4*)&Bsv[r][c] = make_uint4(f2tf(b.x), f2tf(b.y), f2tf(b.z), f2tf(b.w));
        }
        __syncthreads();
#pragma unroll
        for (int kk = 0; kk < 32; kk += 8) {
            unsigned bf[4][2];
#pragma unroll
            for (int t = 0; t < 4; t++) {
                const int n0 = wn * 32 + t * 8 + grp;
                bf[t][0] = Bsv[kk + tig    ][n0];
                bf[t][1] = Bsv[kk + tig + 4][n0];
            }
#pragma unroll
            for (int im = 0; im < 2; im++) {
                const int m0 = wm * 32 + im * 16 + grp;
                unsigned af[4];
                af[0] = As[m0    ][kk + tig];
                af[1] = As[m0 + 8][kk + tig];
                af[2] = As[m0    ][kk + tig + 4];
                af[3] = As[m0 + 8][kk + tig + 4];
#pragma unroll
                for (int t = 0; t < 4; t++) mma8(acc[im][t], af, bf[t]);
            }
        }
        __syncthreads();
    }

    const int b = bh / HH, h = bh % HH;
#pragma unroll
    for (int im = 0; im < 2; im++) {
        const int s0 = bm + wm * 32 + im * 16 + grp;
        const int s1 = s0 + 8;
#pragma unroll
        for (int t = 0; t < 4; t++) {
            const int col = wn * 32 + t * 8 + tig * 2;     // 0..62 even
            float* p0 = g_ctx + (size_t)(b * SS + s0) * CC + h * HDM + col;
            float* p1 = g_ctx + (size_t)(b * SS + s1) * CC + h * HDM + col;
            *(float2*)p0 = make_float2(acc[im][t][0], acc[im][t][1]);
            *(float2*)p1 = make_float2(acc[im][t][2], acc[im][t][3]);
        }
    }
}

// ---------------------------------------------------------------------------
// Kernel 6: out = ctx @ w_out^T + b_out   (tf32 mma). M=8192, N=768, K=768.
// ---------------------------------------------------------------------------
__global__ __launch_bounds__(256) void k_proj(const float* __restrict__ W,
                                              const float* __restrict__ bias,
                                              float* __restrict__ out) {
    __shared__ __align__(16) unsigned As[128][36];
    __shared__ __align__(16) unsigned Bs[128][36];
    const int bm = blockIdx.y * 128;
    const int bn = blockIdx.x * 128;

    float acc[2][8][4];
#pragma unroll
    for (int i = 0; i < 2; i++)
#pragma unroll
        for (int t = 0; t < 8; t++)
#pragma unroll
            for (int v = 0; v < 4; v++) acc[i][t][v] = 0.f;

    gemm_tile_128x128(g_ctx + (size_t)bm * CC, CC, W + (size_t)bn * CC, CC, CC, As, Bs, acc);

    const int tid = threadIdx.x;
    const int lane = tid & 31, warp = tid >> 5;
    const int wm = warp >> 1, wn = warp & 1;
    const int grp = lane >> 2, tig = lane & 3;

#pragma unroll
    for (int im = 0; im < 2; im++) {
        const int r0 = bm + wm * 32 + im * 16 + grp;
        const int r1 = r0 + 8;
#pragma unroll
        for (int t = 0; t < 8; t++) {
            const int col = bn + wn * 64 + t * 8 + tig * 2;
            const float bz0 = bias[col], bz1 = bias[col + 1];
            *(float2*)(out + (size_t)r0 * CC + col) =
                make_float2(acc[im][t][0] + bz0, acc[im][t][1] + bz1);
            *(float2*)(out + (size_t)r1 * CC + col) =
                make_float2(acc[im][t][2] + bz0, acc[im][t][3] + bz1);
        }
    }
}

// ---------------------------------------------------------------------------
extern "C" void kernel_launch(void* const* d_in, const int* in_sizes, int n_in,
                              void* d_out, int out_size) {
    const float* x     = (const float*)d_in[0];
    const float* w_qkv = (const float*)d_in[1];
    const float* w_out = (const float*)d_in[2];
    const float* b_out = (const float*)d_in[3];
    const float* rph   = (const float*)d_in[4];
    const float* rpw   = (const float*)d_in[5];
    float* out = (float*)d_out;

    k_qkv    <<<dim3(2304/128, 8192/128), 256>>>(x, w_qkv);
    k_rel    <<<dim3(BHN, QQ), 256>>>(rph, rpw);
    k_scores <<<dim3(8, 8, BHN), 256>>>();
    k_softmax<<<dim3(BHN * SS), 256>>>();
    k_av     <<<dim3(8, BHN), 256>>>();
    k_proj   <<<dim3(768/128, 8192/128), 256>>>(w_out, b_out, out);
}

// round 17
// speedup vs baseline: 2.9094x; 1.2832x over previous
#include <cuda_runtime.h>
#include <cstdint>

// Problem constants
#define BB   8
#define SS   1024
#define CC   768
#define HH   12
#define HDM  64
#define BHN  (BB*HH)     // 96
#define QQ   32

// Scratch (static device allocations — no cudaMalloc allowed)
__device__ float g_q[BHN*SS*HDM];                 // (bh, s, d)
__device__ float g_k[BHN*SS*HDM];
__device__ float g_v[BHN*SS*HDM];
__device__ float g_relh[BHN*QQ*QQ*QQ];            // (bh, x, ti)   x = qi*32+qj
__device__ float g_relw[BHN*QQ*QQ*QQ];            // (bh, x, tj)
__device__ float g_ctx[BB*SS*CC];                 // (b, s, h*64+d)

// ---------------------------------------------------------------------------
// tf32 helpers
// ---------------------------------------------------------------------------
__device__ __forceinline__ unsigned f2tf(float x) {
    unsigned u;
    asm("cvt.rna.tf32.f32 %0, %1;" : "=r"(u) : "f"(x));
    return u;
}

__device__ __forceinline__ void mma8(float* c, const unsigned* a, const unsigned* b) {
    asm volatile(
        "mma.sync.aligned.m16n8k8.row.col.f32.tf32.tf32.f32 "
        "{%0,%1,%2,%3}, {%4,%5,%6,%7}, {%8,%9}, {%0,%1,%2,%3};"
        : "+f"(c[0]), "+f"(c[1]), "+f"(c[2]), "+f"(c[3])
        : "r"(a[0]), "r"(a[1]), "r"(a[2]), "r"(a[3]), "r"(b[0]), "r"(b[1]));
}

// ---------------------------------------------------------------------------
// Shared 128x128 GEMM mainloop: C[128,128] = A[128,K] * B[128,K]^T
// ---------------------------------------------------------------------------
__device__ __forceinline__ void gemm_tile_128x128(
    const float* __restrict__ A, int lda,
    const float* __restrict__ B, int ldb,
    int K, unsigned (*As)[36], unsigned (*Bs)[36],
    float acc[2][8][4])
{
    const int tid  = threadIdx.x;
    const int lane = tid & 31;
    const int warp = tid >> 5;
    const int wm = warp >> 1;
    const int wn = warp & 1;
    const int grp = lane >> 2;
    const int tig = lane & 3;

    for (int k0 = 0; k0 < K; k0 += 32) {
#pragma unroll
        for (int i = 0; i < 4; i++) {
            const int idx = tid + i * 256;
            const int r = idx >> 3;
            const int c = (idx & 7) * 4;
            float4 a = *(const float4*)(A + (size_t)r * lda + k0 + c);
            *(uint4*)&As[r][c] = make_uint4(f2tf(a.x), f2tf(a.y), f2tf(a.z), f2tf(a.w));
            float4 b = *(const float4*)(B + (size_t)r * ldb + k0 + c);
            *(uint4*)&Bs[r][c] = make_uint4(f2tf(b.x), f2tf(b.y), f2tf(b.z), f2tf(b.w));
        }
        __syncthreads();
#pragma unroll
        for (int kk = 0; kk < 32; kk += 8) {
            unsigned bf[8][2];
#pragma unroll
            for (int t = 0; t < 8; t++) {
                const int n0 = wn * 64 + t * 8 + grp;
                bf[t][0] = Bs[n0][kk + tig];
                bf[t][1] = Bs[n0][kk + tig + 4];
            }
#pragma unroll
            for (int im = 0; im < 2; im++) {
                const int m0 = wm * 32 + im * 16 + grp;
                unsigned af[4];
                af[0] = As[m0    ][kk + tig];
                af[1] = As[m0 + 8][kk + tig];
                af[2] = As[m0    ][kk + tig + 4];
                af[3] = As[m0 + 8][kk + tig + 4];
#pragma unroll
                for (int t = 0; t < 8; t++) mma8(acc[im][t], af, bf[t]);
            }
        }
        __syncthreads();
    }
}

// ---------------------------------------------------------------------------
// Kernel 1: qkv = x @ w_qkv^T, scattered into q/k/v (bh, s, d).
// ---------------------------------------------------------------------------
__global__ __launch_bounds__(256) void k_qkv(const float* __restrict__ X,
                                             const float* __restrict__ W) {
    __shared__ __align__(16) unsigned As[128][36];
    __shared__ __align__(16) unsigned Bs[128][36];
    const int bm = blockIdx.y * 128;
    const int bn = blockIdx.x * 128;

    float acc[2][8][4];
#pragma unroll
    for (int i = 0; i < 2; i++)
#pragma unroll
        for (int t = 0; t < 8; t++)
#pragma unroll
            for (int v = 0; v < 4; v++) acc[i][t][v] = 0.f;

    gemm_tile_128x128(X + (size_t)bm * CC, CC, W + (size_t)bn * CC, CC, CC, As, Bs, acc);

    const int tid = threadIdx.x;
    const int lane = tid & 31, warp = tid >> 5;
    const int wm = warp >> 1, wn = warp & 1;
    const int grp = lane >> 2, tig = lane & 3;

#pragma unroll
    for (int im = 0; im < 2; im++) {
        const int r0 = bm + wm * 32 + im * 16 + grp;
        const int r1 = r0 + 8;
        const int b0i = r0 >> 10, s0 = r0 & 1023;
        const int b1i = r1 >> 10, s1 = r1 & 1023;
#pragma unroll
        for (int t = 0; t < 8; t++) {
            const int col  = bn + wn * 64 + t * 8 + tig * 2;
            const int part = col / CC;
            const int rem  = col - part * CC;
            const int h = rem >> 6, d = rem & 63;
            float* dst = (part == 0) ? g_q : ((part == 1) ? g_k : g_v);
            float* p0 = dst + ((size_t)(b0i * HH + h) * SS + s0) * HDM + d;
            float* p1 = dst + ((size_t)(b1i * HH + h) * SS + s1) * HDM + d;
            *(float2*)p0 = make_float2(acc[im][t][0], acc[im][t][1]);
            *(float2*)p1 = make_float2(acc[im][t][2], acc[im][t][3]);
        }
    }
}

// ---------------------------------------------------------------------------
// Kernel 2: decomposed rel-pos tables (fp32).
// ---------------------------------------------------------------------------
__global__ __launch_bounds__(256) void k_rel(const float* __restrict__ rph,
                                             const float* __restrict__ rpw) {
    __shared__ float Qs[32][64];
    __shared__ float Rh[32][64];
    __shared__ float Rw[63][64];
    const int bh = blockIdx.x;
    const int qi = blockIdx.y;
    const int tid = threadIdx.x;
    const float* qp = g_q + ((size_t)bh * SS + (size_t)qi * QQ) * HDM;

    for (int idx = tid; idx < 32 * 64; idx += 256) {
        const int r = idx >> 6, d = idx & 63;
        Qs[r][d] = qp[(size_t)r * HDM + d];
        Rh[r][d] = rph[(size_t)(qi - r + 31) * HDM + d];
    }
    for (int idx = tid; idx < 63 * 64; idx += 256) {
        Rw[idx >> 6][idx & 63] = rpw[idx];
    }
    __syncthreads();

    float* relh = g_relh + ((size_t)bh * QQ + qi) * QQ * QQ;
    float* relw = g_relw + ((size_t)bh * QQ + qi) * QQ * QQ;
    for (int p = tid; p < 32 * 32; p += 256) {
        const int j = p >> 5, t = p & 31;
        const float* qrow = Qs[j];
        const float* rhr  = Rh[t];
        const float* rwr  = Rw[j - t + 31];
        float sh = 0.f, sw = 0.f;
#pragma unroll
        for (int d = 0; d < 64; d++) {
            sh += qrow[d] * rhr[d];
            sw += qrow[d] * rwr[d];
        }
        relh[(size_t)j * QQ + t] = sh;
        relw[(size_t)j * QQ + t] = sw;
    }
}

// ---------------------------------------------------------------------------
// Kernel 3: fused flash attention.
// Per block: 128 Q rows of one (b,h), loop over 16 KV tiles of 64.
// Warp owns a 16-row stripe across all columns; online softmax per row pair.
// Smem: Ps[128][68] (pitch 68: conflict-free A-frag reads),
//       Ks[64][68]  ([n][k], conflict-free B-frag reads),
//       Vs[64][64]  ([k][n] XOR-8 swizzled: conflict-free B-frag reads).
// ---------------------------------------------------------------------------
extern __shared__ unsigned fl_smem[];

__global__ __launch_bounds__(256) void k_flash() {
    const int bh    = blockIdx.y;
    const int qbase = blockIdx.x * 128;
    const int tid   = threadIdx.x;
    const int lane  = tid & 31, warp = tid >> 5;
    const int grp   = lane >> 2, tig = lane & 3;

    unsigned* Ps = fl_smem;              // 128*68
    unsigned* Ks = Ps + 128 * 68;        // 64*68
    unsigned* Vs = Ks + 64 * 68;         // 64*64

    const float* Q = g_q + (size_t)bh * SS * HDM;
    const float* K = g_k + (size_t)bh * SS * HDM;
    const float* V = g_v + (size_t)bh * SS * HDM;

    const int xa = qbase + warp * 16 + grp;   // row A (global q index)
    const int xb = xa + 8;                    // row B

    // Q fragments in registers for the whole kernel
    unsigned qa[8][4];
    {
        const float* Qa = Q + (size_t)xa * HDM;
        const float* Qb = Q + (size_t)xb * HDM;
#pragma unroll
        for (int ks = 0; ks < 8; ks++) {
            qa[ks][0] = f2tf(Qa[ks * 8 + tig]);
            qa[ks][1] = f2tf(Qb[ks * 8 + tig]);
            qa[ks][2] = f2tf(Qa[ks * 8 + tig + 4]);
            qa[ks][3] = f2tf(Qb[ks * 8 + tig + 4]);
        }
    }

    // rel-pos rows (x-indexed); rw pattern is kv-invariant -> hoist
    const float* rh_a = g_relh + ((size_t)bh * SS + xa) * QQ;
    const float* rh_b = g_relh + ((size_t)bh * SS + xb) * QQ;
    const float* rw_a = g_relw + ((size_t)bh * SS + xa) * QQ;
    const float* rw_b = g_relw + ((size_t)bh * SS + xb) * QQ;
    float rwa[4][2], rwb[4][2];
#pragma unroll
    for (int j = 0; j < 4; j++) {
        rwa[j][0] = rw_a[j * 8 + tig * 2]; rwa[j][1] = rw_a[j * 8 + tig * 2 + 1];
        rwb[j][0] = rw_b[j * 8 + tig * 2]; rwb[j][1] = rw_b[j * 8 + tig * 2 + 1];
    }

    float o[8][4];
#pragma unroll
    for (int t = 0; t < 8; t++)
#pragma unroll
        for (int v = 0; v < 4; v++) o[t][v] = 0.f;
    float m_a = -1e30f, m_b = -1e30f, l_a = 0.f, l_b = 0.f;

    for (int kv = 0; kv < 16; kv++) {
        // ---- load K (64x64, [n][k] pitch 68) and V (64x64, [k][n] xor-swizzle)
#pragma unroll
        for (int i = 0; i < 4; i++) {
            const int idx = tid + i * 256;       // 0..1023
            const int r = idx >> 4;              // 0..63
            const int c = (idx & 15) * 4;        // 0..60
            float4 kk4 = *(const float4*)(K + (size_t)(kv * 64 + r) * HDM + c);
            *(uint4*)&Ks[r * 68 + c] =
                make_uint4(f2tf(kk4.x), f2tf(kk4.y), f2tf(kk4.z), f2tf(kk4.w));
            float4 vv4 = *(const float4*)(V + (size_t)(kv * 64 + r) * HDM + c);
            *(uint4*)&Vs[r * 64 + (c ^ ((r & 3) * 8))] =
                make_uint4(f2tf(vv4.x), f2tf(vv4.y), f2tf(vv4.z), f2tf(vv4.w));
        }
        __syncthreads();

        // ---- S = Q K^T  (warp: 16 rows x 64 cols, 8 n-tiles, 8 k-steps)
        float s[8][4];
#pragma unroll
        for (int t = 0; t < 8; t++)
#pragma unroll
            for (int v = 0; v < 4; v++) s[t][v] = 0.f;
#pragma unroll
        for (int ks = 0; ks < 8; ks++) {
#pragma unroll
            for (int t = 0; t < 8; t++) {
                unsigned bf[2];
                const int n0 = t * 8 + grp;
                bf[0] = Ks[n0 * 68 + ks * 8 + tig];
                bf[1] = Ks[n0 * 68 + ks * 8 + tig + 4];
                mma8(s[t], qa[ks], bf);
            }
        }

        // ---- bias + scale, tile row max
        const float rha0 = rh_a[kv * 2], rha1 = rh_a[kv * 2 + 1];
        const float rhb0 = rh_b[kv * 2], rhb1 = rh_b[kv * 2 + 1];
        float vmax_a = -1e30f, vmax_b = -1e30f;
#pragma unroll
        for (int t = 0; t < 8; t++) {
            const float ha = (t < 4) ? rha0 : rha1;
            const float hb = (t < 4) ? rhb0 : rhb1;
            const int j = t & 3;
            s[t][0] = s[t][0] * 0.125f + ha + rwa[j][0];
            s[t][1] = s[t][1] * 0.125f + ha + rwa[j][1];
            s[t][2] = s[t][2] * 0.125f + hb + rwb[j][0];
            s[t][3] = s[t][3] * 0.125f + hb + rwb[j][1];
            vmax_a = fmaxf(vmax_a, fmaxf(s[t][0], s[t][1]));
            vmax_b = fmaxf(vmax_b, fmaxf(s[t][2], s[t][3]));
        }
        vmax_a = fmaxf(vmax_a, __shfl_xor_sync(0xffffffffu, vmax_a, 1));
        vmax_a = fmaxf(vmax_a, __shfl_xor_sync(0xffffffffu, vmax_a, 2));
        vmax_b = fmaxf(vmax_b, __shfl_xor_sync(0xffffffffu, vmax_b, 1));
        vmax_b = fmaxf(vmax_b, __shfl_xor_sync(0xffffffffu, vmax_b, 2));

        const float mn_a = fmaxf(m_a, vmax_a);
        const float mn_b = fmaxf(m_b, vmax_b);
        const float al_a = __expf(m_a - mn_a);
        const float al_b = __expf(m_b - mn_b);
        m_a = mn_a; m_b = mn_b;

        // ---- P = exp(S - m), write to smem (tf32), accumulate row sums
        float sum_a = 0.f, sum_b = 0.f;
        const int rowA = (warp * 16 + grp) * 68;
        const int rowB = rowA + 8 * 68;
#pragma unroll
        for (int t = 0; t < 8; t++) {
            const float p0 = __expf(s[t][0] - m_a);
            const float p1 = __expf(s[t][1] - m_a);
            const float p2 = __expf(s[t][2] - m_b);
            const float p3 = __expf(s[t][3] - m_b);
            sum_a += p0 + p1; sum_b += p2 + p3;
            const int col = t * 8 + tig * 2;
            Ps[rowA + col]     = f2tf(p0);
            Ps[rowA + col + 1] = f2tf(p1);
            Ps[rowB + col]     = f2tf(p2);
            Ps[rowB + col + 1] = f2tf(p3);
        }
        sum_a += __shfl_xor_sync(0xffffffffu, sum_a, 1);
        sum_a += __shfl_xor_sync(0xffffffffu, sum_a, 2);
        sum_b += __shfl_xor_sync(0xffffffffu, sum_b, 1);
        sum_b += __shfl_xor_sync(0xffffffffu, sum_b, 2);
        l_a = l_a * al_a + sum_a;
        l_b = l_b * al_b + sum_b;

        // rescale O
#pragma unroll
        for (int t = 0; t < 8; t++) {
            o[t][0] *= al_a; o[t][1] *= al_a;
            o[t][2] *= al_b; o[t][3] *= al_b;
        }
        __syncthreads();   // P visible to all lanes of this warp's stripe reads

        // ---- O += P (16x64) * V (64x64)
#pragma unroll
        for (int ks = 0; ks < 8; ks++) {
            unsigned af[4];
            af[0] = Ps[rowA + ks * 8 + tig];
            af[1] = Ps[rowB + ks * 8 + tig];
            af[2] = Ps[rowA + ks * 8 + tig + 4];
            af[3] = Ps[rowB + ks * 8 + tig + 4];
#pragma unroll
            for (int t = 0; t < 8; t++) {
                unsigned bf[2];
                const int n0 = (t * 8 + grp) ^ (tig * 8);
                bf[0] = Vs[(ks * 8 + tig)     * 64 + n0];
                bf[1] = Vs[(ks * 8 + tig + 4) * 64 + n0];
                mma8(o[t], af, bf);
            }
        }
        __syncthreads();   // before next K/V tile overwrites smem
    }

    // ---- epilogue: normalize and write ctx
    const float inva = 1.f / l_a, invb = 1.f / l_b;
    const int b = bh / HH, h = bh % HH;
    float* da = g_ctx + (size_t)(b * SS + xa) * CC + h * HDM;
    float* db = g_ctx + (size_t)(b * SS + xb) * CC + h * HDM;
#pragma unroll
    for (int t = 0; t < 8; t++) {
        const int col = t * 8 + tig * 2;
        *(float2*)(da + col) = make_float2(o[t][0] * inva, o[t][1] * inva);
        *(float2*)(db + col) = make_float2(o[t][2] * invb, o[t][3] * invb);
    }
}

// ---------------------------------------------------------------------------
// Kernel 4: out = ctx @ w_out^T + b_out   (tf32 mma). M=8192, N=768, K=768.
// ---------------------------------------------------------------------------
__global__ __launch_bounds__(256) void k_proj(const float* __restrict__ W,
                                              const float* __restrict__ bias,
                                              float* __restrict__ out) {
    __shared__ __align__(16) unsigned As[128][36];
    __shared__ __align__(16) unsigned Bs[128][36];
    const int bm = blockIdx.y * 128;
    const int bn = blockIdx.x * 128;

    float acc[2][8][4];
#pragma unroll
    for (int i = 0; i < 2; i++)
#pragma unroll
        for (int t = 0; t < 8; t++)
#pragma unroll
            for (int v = 0; v < 4; v++) acc[i][t][v] = 0.f;

    gemm_tile_128x128(g_ctx + (size_t)bm * CC, CC, W + (size_t)bn * CC, CC, CC, As, Bs, acc);

    const int tid = threadIdx.x;
    const int lane = tid & 31, warp = tid >> 5;
    const int wm = warp >> 1, wn = warp & 1;
    const int grp = lane >> 2, tig = lane & 3;

#pragma unroll
    for (int im = 0; im < 2; im++) {
        const int r0 = bm + wm * 32 + im * 16 + grp;
        const int r1 = r0 + 8;
#pragma unroll
        for (int t = 0; t < 8; t++) {
            const int col = bn + wn * 64 + t * 8 + tig * 2;
            const float bz0 = bias[col], bz1 = bias[col + 1];
            *(float2*)(out + (size_t)r0 * CC + col) =
                make_float2(acc[im][t][0] + bz0, acc[im][t][1] + bz1);
            *(float2*)(out + (size_t)r1 * CC + col) =
                make_float2(acc[im][t][2] + bz0, acc[im][t][3] + bz1);
        }
    }
}

// ---------------------------------------------------------------------------
extern "C" void kernel_launch(void* const* d_in, const int* in_sizes, int n_in,
                              void* d_out, int out_size) {
    const float* x     = (const float*)d_in[0];
    const float* w_qkv = (const float*)d_in[1];
    const float* w_out = (const float*)d_in[2];
    const float* b_out = (const float*)d_in[3];
    const float* rph   = (const float*)d_in[4];
    const float* rpw   = (const float*)d_in[5];
    float* out = (float*)d_out;

    const int fl_bytes = (128 * 68 + 64 * 68 + 64 * 64) * 4;   // 68608
    cudaFuncSetAttribute(k_flash, cudaFuncAttributeMaxDynamicSharedMemorySize, fl_bytes);

    k_qkv  <<<dim3(2304/128, 8192/128), 256>>>(x, w_qkv);
    k_rel  <<<dim3(BHN, QQ), 256>>>(rph, rpw);
    k_flash<<<dim3(8, BHN), 256, fl_bytes>>>();
    k_proj <<<dim3(768/128, 8192/128), 256>>>(w_out, b_out, out);
}